// round 11
// baseline (speedup 1.0000x reference)
#include <cuda_runtime.h>
#include <cstddef>
#include <cstdint>

// GRU_83133386982146: 2-layer GRU (H=10) + per-step linear 10->1.
// R11 = R9 role-partition (1 batch/warp, 1024 warps) with:
//  - state broadcast via 10 per-lane-source SHFLs + 5 packs (no smem/syncwarp)
//  - sigmoid-side weights pre-scaled by 0.5 (kills the mul before MUFU.TANH)
//  - output linear fused back in (off-chain FFMA2 dot + 1 publish shfl),
//    coalesced 128B out store per 32 steps; no second kernel, no h1 planes.
//   lanes  0- 9: L0 unit k  (Whh0 rows . h0v), gates local
//   lanes 10-19: L1 ih dots (Wih1 rows . h0v)
//   lanes 20-29: L1 hh dots (Whh1 rows . h1v) + L1 gates + h1 update + out dot

#define FULL 0xffffffffu

namespace {
constexpr int H = 10;
constexpr int T = 2048;
constexpr int B = 1024;
}

__device__ __forceinline__ float fast_tanh(float x) {
    float y;
    asm("tanh.approx.f32 %0, %1;" : "=f"(y) : "f"(x));
    return y;
}
__device__ __forceinline__ uint64_t pack2(float lo, float hi) {
    uint64_t r;
    asm("mov.b64 %0, {%1, %2};" : "=l"(r) : "f"(lo), "f"(hi));
    return r;
}
__device__ __forceinline__ float hadd2(uint64_t a) {
    float lo, hi;
    asm("mov.b64 {%0, %1}, %2;" : "=f"(lo), "=f"(hi) : "l"(a));
    return lo + hi;
}
__device__ __forceinline__ uint64_t ffma2(uint64_t a, uint64_t b, uint64_t c) {
    uint64_t d;
    asm("fma.rn.f32x2 %0, %1, %2, %3;" : "=l"(d) : "l"(a), "l"(b), "l"(c));
    return d;
}

__global__ void __launch_bounds__(32)
gru_warp_kernel(const float* __restrict__ x,
                const float* __restrict__ Wih0, const float* __restrict__ Whh0,
                const float* __restrict__ bih0, const float* __restrict__ bhh0,
                const float* __restrict__ Wih1, const float* __restrict__ Whh1,
                const float* __restrict__ bih1, const float* __restrict__ bhh1,
                const float* __restrict__ Wlin, const float* __restrict__ blin,
                float* __restrict__ out)
{
    const int b = blockIdx.x;
    const int lane = threadIdx.x;
    const int cl = (lane < 30) ? lane : 29;
    const bool isL0 = (lane < 10);
    const bool isIH = (lane >= 10 && lane < 20);
    const bool isHH = (lane >= 20);
    const int k = cl % 10;

    const float* Wsrc = isL0 ? Whh0 : (isIH ? Wih1 : Whh1);

    // packed gate-row weights; A(=r), B(=z) pre-scaled by 0.5 (feed sigmoid)
    uint64_t wa[5], wb[5], wc[5], wl[5];
#pragma unroll
    for (int j = 0; j < 5; j++) {
        wa[j] = pack2(0.5f * Wsrc[k * H + 2 * j],
                      0.5f * Wsrc[k * H + 2 * j + 1]);
        wb[j] = pack2(0.5f * Wsrc[(H + k) * H + 2 * j],
                      0.5f * Wsrc[(H + k) * H + 2 * j + 1]);
        wc[j] = pack2(Wsrc[(2 * H + k) * H + 2 * j],
                      Wsrc[(2 * H + k) * H + 2 * j + 1]);
        wl[j] = pack2(Wlin[2 * j], Wlin[2 * j + 1]);
    }
    // layer0 x coefficients (input size 1); A/B halved
    const float cxA = isL0 ? 0.5f * Wih0[k] : 0.0f;
    const float cxB = isL0 ? 0.5f * Wih0[H + k] : 0.0f;
    const float cxC = isL0 ? Wih0[2 * H + k] : 0.0f;
    // dot-chain seeds (lo element); A/B halved
    const float sA = isIH ? 0.5f * bih1[k] : 0.0f;
    const float sB = isIH ? 0.5f * bih1[H + k] : 0.0f;
    const float sC = isL0 ? bhh0[2 * H + k]
                   : (isIH ? bih1[2 * H + k] : bhh1[2 * H + k]);
    const uint64_t seedA = pack2(sA, 0.0f);
    const uint64_t seedB = pack2(sB, 0.0f);
    const uint64_t seedC = pack2(sC, 0.0f);
    // bias adds into the sigmoid pre-acts (halved); C-side not halved
    const float btA = isL0 ? 0.5f * (bih0[k] + bhh0[k])
                           : (isHH ? 0.5f * bhh1[k] : 0.0f);
    const float btB = isL0 ? 0.5f * (bih0[H + k] + bhh0[H + k])
                           : (isHH ? 0.5f * bhh1[H + k] : 0.0f);
    const float btC = isL0 ? bih0[2 * H + k] : 0.0f;
    const float sel = isHH ? 1.0f : 0.0f;
    const int csrc = isHH ? (lane - 10) : lane;    // combine source (IH dot)
    const int vsrc = (lane < 20) ? 0 : 20;         // broadcast source base
    const uint64_t seedO = pack2(blin[0], 0.0f);

    const float* xq = x + (size_t)b * T;
    float* orow = out + (size_t)b * T;

    float hown;
    uint64_t v[5];

    // ---- preamble: h0(0)  (h(-1)=0 -> hidden dots vanish) ----
    {
        const float x0 = xq[0];
        const float pA = fmaf(cxA, x0, btA);           // already 0.5-scaled
        const float pB = fmaf(cxB, x0, btB);
        const float tC = fmaf(cxC, x0, btC);
        const float r = fmaf(fast_tanh(pA), 0.5f, 0.5f);
        const float z = fmaf(fast_tanh(pB), 0.5f, 0.5f);
        const float n = fast_tanh(fmaf(r, sC, tC));
        const float h0n = fmaf(z, 0.0f - n, n);        // valid on L0 lanes
        const float hnew = isL0 ? h0n : 0.0f;          // h1(-1) = 0
        hown = hnew;
#pragma unroll
        for (int j = 0; j < 5; j++) {
            const float lo = __shfl_sync(FULL, hnew, vsrc + 2 * j);
            const float hi = __shfl_sync(FULL, hnew, vsrc + 2 * j + 1);
            v[j] = pack2(lo, hi);
        }
    }

    float xc = xq[1];          // x(t+1) for iteration t=0
    float obuf = 0.0f;

    // Invariant: v = h0(t) on lanes<20, h1(t-1) on lanes>=20; xc = x(t+1).
#pragma unroll 4
    for (int t = 0; t < T; t++) {
        const int xi = (t + 2 < T) ? (t + 2) : (T - 1);
        const float xn_pref = xq[xi];

        // 3 packed dot chains (5 FFMA2 each)
        uint64_t aA = seedA, aB = seedB, aC = seedC;
#pragma unroll
        for (int j = 0; j < 5; j++) {
            aA = ffma2(wa[j], v[j], aA);
            aB = ffma2(wb[j], v[j], aB);
            aC = ffma2(wc[j], v[j], aC);
        }
        const float dotA = hadd2(aA);
        const float dotB = hadd2(aB);
        const float dotC = hadd2(aC);

        // HH lanes pull matching IH dots (A/B already half-scaled there)
        const float gA = __shfl_sync(FULL, dotA, csrc);
        const float gB = __shfl_sync(FULL, dotB, csrc);
        const float gC = __shfl_sync(FULL, dotC, csrc);

        const float tA = fmaf(cxA, xc, btA);
        const float tB = fmaf(cxB, xc, btB);
        const float tC = fmaf(cxC, xc, btC);

        const float preA = fmaf(sel, gA, dotA + tA);   // 0.5 * (r pre-act)
        const float preB = fmaf(sel, gB, dotB + tB);   // 0.5 * (z pre-act)
        const float r = fmaf(fast_tanh(preA), 0.5f, 0.5f);
        const float z = fmaf(fast_tanh(preB), 0.5f, 0.5f);
        const float q = fmaf(sel, gC, tC);
        const float n = fast_tanh(fmaf(r, dotC, q));
        const float hnew = fmaf(z, hown - n, n);       // h0(t+1) | h1(t)
        hown = hnew;

        // broadcast: each lane rebuilds its packed vector (10 shfl + 5 pack)
#pragma unroll
        for (int j = 0; j < 5; j++) {
            const float lo = __shfl_sync(FULL, hnew, vsrc + 2 * j);
            const float hi = __shfl_sync(FULL, hnew, vsrc + 2 * j + 1);
            v[j] = pack2(lo, hi);
        }

        // out(t) = Wlin . h1(t) + bl  (off-chain; v = h1v on HH lanes)
        uint64_t aO = seedO;
#pragma unroll
        for (int j = 0; j < 5; j++) aO = ffma2(wl[j], v[j], aO);
        const float val = __shfl_sync(FULL, hadd2(aO), 20);   // uniform
        if ((t & 31) == lane) obuf = val;
        if ((t & 31) == 31) orow[(t & ~31) + lane] = obuf;    // 128B coalesced

        xc = xn_pref;
    }
}

extern "C" void kernel_launch(void* const* d_in, const int* in_sizes, int n_in,
                              void* d_out, int out_size) {
    (void)in_sizes; (void)n_in; (void)out_size;
    const float* x    = (const float*)d_in[0];
    const float* Wih0 = (const float*)d_in[1];
    const float* Whh0 = (const float*)d_in[2];
    const float* bih0 = (const float*)d_in[3];
    const float* bhh0 = (const float*)d_in[4];
    const float* Wih1 = (const float*)d_in[5];
    const float* Whh1 = (const float*)d_in[6];
    const float* bih1 = (const float*)d_in[7];
    const float* bhh1 = (const float*)d_in[8];
    const float* Wlin = (const float*)d_in[9];
    const float* blin = (const float*)d_in[10];
    float* out = (float*)d_out;

    gru_warp_kernel<<<B, 32>>>(x, Wih0, Whh0, bih0, bhh0,
                               Wih1, Whh1, bih1, bhh1, Wlin, blin, out);
}

// round 12
// speedup vs baseline: 1.0013x; 1.0013x over previous
#include <cuda_runtime.h>
#include <cstddef>
#include <cstdint>

// GRU_83133386982146: 2-layer GRU (H=10) + per-step linear 10->1.
// R12: no-combine role partition, 1 batch/warp (1024 warps):
//   lanes  0- 9: L0 unit k: chains c0=r,c1=z,c2=n over h0; c3 = OUT dot
//                (Wlin . h1(t-1), seed blin) -- fused output linear.
//   lanes 10-19: L1 unit k: c0..c2 = ih r/z/n over h0; c3..c5 = hh r/z/n
//                over h1. All gate math local -> NO mid-step combine shfl.
//   lanes 20-31: idle mirrors (clamped), STS to scratch.
// Broadcast: smem double-buffered, 1 STS + syncwarp + 6 uniform LDS.128/64
// (both state vectors, packed for fma.rn.f32x2). Sigmoid weights pre-scaled
// by 0.5. Software pipeline: iter t computes h0(t+1), h1(t), out(t-1).

#define FULL 0xffffffffu

namespace {
constexpr int H = 10;
constexpr int T = 2048;
constexpr int B = 1024;
}

__device__ __forceinline__ float fast_tanh(float x) {
    float y;
    asm("tanh.approx.f32 %0, %1;" : "=f"(y) : "f"(x));
    return y;
}
__device__ __forceinline__ uint64_t pack2(float lo, float hi) {
    uint64_t r;
    asm("mov.b64 %0, {%1, %2};" : "=l"(r) : "f"(lo), "f"(hi));
    return r;
}
__device__ __forceinline__ float hadd2(uint64_t a) {
    float lo, hi;
    asm("mov.b64 {%0, %1}, %2;" : "=f"(lo), "=f"(hi) : "l"(a));
    return lo + hi;
}
__device__ __forceinline__ uint64_t ffma2(uint64_t a, uint64_t b, uint64_t c) {
    uint64_t d;
    asm("fma.rn.f32x2 %0, %1, %2, %3;" : "=l"(d) : "l"(a), "l"(b), "l"(c));
    return d;
}

__global__ void __launch_bounds__(32)
gru_warp_kernel(const float* __restrict__ x,
                const float* __restrict__ Wih0, const float* __restrict__ Whh0,
                const float* __restrict__ bih0, const float* __restrict__ bhh0,
                const float* __restrict__ Wih1, const float* __restrict__ Whh1,
                const float* __restrict__ bih1, const float* __restrict__ bhh1,
                const float* __restrict__ Wlin, const float* __restrict__ blin,
                float* __restrict__ out)
{
    const int b = blockIdx.x;
    const int lane = threadIdx.x;
    const bool isL0 = (lane < 10);
    const int k = isL0 ? lane
                : (lane < 20) ? (lane - 10)
                : (lane < 30) ? (lane - 20) : 9;

    // smem: [parity][40 floats]: h0 @0..9, h1 @12..21 (48B), scratch @24..39
    __shared__ __align__(16) float sbuf[2][40];

    // chain weights (packed pairs). A-side source: Whh0 (L0) | Wih1 (L1).
    const float* WA = isL0 ? Whh0 : Wih1;
    uint64_t w0[5], w1[5], w2[5], w3[5], w4[5], w5[5];
#pragma unroll
    for (int j = 0; j < 5; j++) {
        w0[j] = pack2(0.5f * WA[k * H + 2 * j], 0.5f * WA[k * H + 2 * j + 1]);
        w1[j] = pack2(0.5f * WA[(H + k) * H + 2 * j],
                      0.5f * WA[(H + k) * H + 2 * j + 1]);
        w2[j] = pack2(WA[(2 * H + k) * H + 2 * j],
                      WA[(2 * H + k) * H + 2 * j + 1]);
        if (isL0) {
            w3[j] = pack2(Wlin[2 * j], Wlin[2 * j + 1]);    // OUT dot
            w4[j] = pack2(0.0f, 0.0f);
            w5[j] = pack2(0.0f, 0.0f);
        } else {
            w3[j] = pack2(0.5f * Whh1[k * H + 2 * j],
                          0.5f * Whh1[k * H + 2 * j + 1]);
            w4[j] = pack2(0.5f * Whh1[(H + k) * H + 2 * j],
                          0.5f * Whh1[(H + k) * H + 2 * j + 1]);
            w5[j] = pack2(Whh1[(2 * H + k) * H + 2 * j],
                          Whh1[(2 * H + k) * H + 2 * j + 1]);
        }
    }
    // chain seeds (lo element)
    const uint64_t s2 = pack2(isL0 ? bhh0[2 * H + k] : bih1[2 * H + k], 0.0f);
    const uint64_t s3 = pack2(isL0 ? blin[0] : 0.0f, 0.0f);
    const uint64_t s5 = pack2(isL0 ? 0.0f : bhh1[2 * H + k], 0.0f);
    const uint64_t z2 = pack2(0.0f, 0.0f);
    // scalar constants
    const float cxA = isL0 ? 0.5f * Wih0[k] : 0.0f;
    const float cxB = isL0 ? 0.5f * Wih0[H + k] : 0.0f;
    const float cxC = isL0 ? Wih0[2 * H + k] : 0.0f;
    const float btA = isL0 ? 0.5f * (bih0[k] + bhh0[k])
                           : 0.5f * (bih1[k] + bhh1[k]);
    const float btB = isL0 ? 0.5f * (bih0[H + k] + bhh0[H + k])
                           : 0.5f * (bih1[H + k] + bhh1[H + k]);
    const float btC = isL0 ? bih0[2 * H + k] : 0.0f;
    const float selB = isL0 ? 0.0f : 1.0f;

    const int soff = (lane < 10) ? lane
                   : (lane < 20) ? (12 + (lane - 10))
                                 : (24 + (lane - 20));

    const float* xq = x + (size_t)b * T;
    float* orow = out + (size_t)b * T;

    float hown;
    uint64_t vA[5], vB[5];   // h0(t), h1(t-1) — uniform smem addresses

    // ---- preamble: h0(0) (hidden state zero -> dots vanish) ----
    {
        const float x0 = xq[0];
        const float pA = fmaf(cxA, x0, btA);
        const float pB = fmaf(cxB, x0, btB);
        const float tC = fmaf(cxC, x0, btC);
        const float r = fmaf(fast_tanh(pA), 0.5f, 0.5f);
        const float z = fmaf(fast_tanh(pB), 0.5f, 0.5f);
        const float n = fast_tanh(fmaf(r, isL0 ? bhh0[2 * H + k] : 0.0f, tC));
        const float h0n = fmaf(z, 0.0f - n, n);
        hown = isL0 ? h0n : 0.0f;                  // h1(-1) = 0 on L1 lanes
#pragma unroll
        for (int j = 0; j < 5; j++) {
            const float lo = __shfl_sync(FULL, h0n, 2 * j);
            const float hi = __shfl_sync(FULL, h0n, 2 * j + 1);
            vA[j] = pack2(lo, hi);
            vB[j] = z2;
        }
    }

    float xc = xq[1];
    float obuf = 0.0f;

    // Invariant: vA = h0(t), vB = h1(t-1); hown = h0(t)_k | h1(t-1)_k.
    // Iter t computes h0(t+1), h1(t), and out(t-1) (= c3 over vB, L0 lanes).
#pragma unroll 2
    for (int t = 0; t < T; t++) {
        const int xi = (t + 2 < T) ? (t + 2) : (T - 1);
        const float xn_pref = xq[xi];

        // 6 packed chains, 5 FFMA2 each
        uint64_t a0 = z2, a1 = z2, a2 = s2, a3 = s3, a4 = z2, a5 = s5;
#pragma unroll
        for (int j = 0; j < 5; j++) {
            a0 = ffma2(w0[j], vA[j], a0);
            a1 = ffma2(w1[j], vA[j], a1);
            a2 = ffma2(w2[j], vA[j], a2);
            a3 = ffma2(w3[j], vB[j], a3);
            a4 = ffma2(w4[j], vB[j], a4);
            a5 = ffma2(w5[j], vB[j], a5);
        }
        const float c0 = hadd2(a0), c1 = hadd2(a1), c2 = hadd2(a2);
        const float c3 = hadd2(a3), c4 = hadd2(a4), c5 = hadd2(a5);

        const float tA = fmaf(cxA, xc, btA);
        const float tB = fmaf(cxB, xc, btB);
        const float tC = fmaf(cxC, xc, btC);

        const float preR = fmaf(selB, c3, c0 + tA);    // 0.5 * r pre-act
        const float preZ = fmaf(selB, c4, c1 + tB);    // 0.5 * z pre-act
        const float r = fmaf(fast_tanh(preR), 0.5f, 0.5f);
        const float z = fmaf(fast_tanh(preZ), 0.5f, 0.5f);
        const float P = isL0 ? c2 : c5;                // FSEL
        const float Q = fmaf(selB, c2, tC);
        const float n = fast_tanh(fmaf(r, P, Q));
        const float hnew = fmaf(z, hown - n, n);       // h0(t+1) | h1(t)
        hown = hnew;

        // broadcast (double-buffered smem, uniform reload addresses)
        const int p = t & 1;
        sbuf[p][soff] = hnew;
        __syncwarp();
        {
            const ulonglong2 A0 = *(const ulonglong2*)&sbuf[p][0];
            const ulonglong2 A1 = *(const ulonglong2*)&sbuf[p][4];
            vA[0] = A0.x; vA[1] = A0.y; vA[2] = A1.x; vA[3] = A1.y;
            vA[4] = *(const uint64_t*)&sbuf[p][8];
            const ulonglong2 B0 = *(const ulonglong2*)&sbuf[p][12];
            const ulonglong2 B1 = *(const ulonglong2*)&sbuf[p][16];
            vB[0] = B0.x; vB[1] = B0.y; vB[2] = B1.x; vB[3] = B1.y;
            vB[4] = *(const uint64_t*)&sbuf[p][20];
        }

        // stage out(t-1): slot (t-1)%10; store 10 rows every 10 steps
        const int tm1 = t - 1;
        if (lane == tm1 % 10 && t > 0) obuf = c3;      // (t=0: no stage)
        if (t > 0 && (tm1 % 10) == 9 && lane < 10)
            orow[tm1 - 9 + lane] = obuf;
        xc = xn_pref;
    }

    // epilogue: out(T-1) from vB = h1(T-1); rows 2040..2047 pending
    {
        uint64_t a3 = s3;
#pragma unroll
        for (int j = 0; j < 5; j++) a3 = ffma2(w3[j], vB[j], a3);
        const float oval = hadd2(a3);
        if (lane == ((T - 1) % 10)) obuf = oval;
        if (lane < 8) orow[2040 + lane] = obuf;
    }
}

extern "C" void kernel_launch(void* const* d_in, const int* in_sizes, int n_in,
                              void* d_out, int out_size) {
    (void)in_sizes; (void)n_in; (void)out_size;
    const float* x    = (const float*)d_in[0];
    const float* Wih0 = (const float*)d_in[1];
    const float* Whh0 = (const float*)d_in[2];
    const float* bih0 = (const float*)d_in[3];
    const float* bhh0 = (const float*)d_in[4];
    const float* Wih1 = (const float*)d_in[5];
    const float* Whh1 = (const float*)d_in[6];
    const float* bih1 = (const float*)d_in[7];
    const float* bhh1 = (const float*)d_in[8];
    const float* Wlin = (const float*)d_in[9];
    const float* blin = (const float*)d_in[10];
    float* out = (float*)d_out;

    gru_warp_kernel<<<B, 32>>>(x, Wih0, Whh0, bih0, bhh0,
                               Wih1, Whh1, bih1, bhh1, Wlin, blin, out);
}

// round 14
// speedup vs baseline: 1.0419x; 1.0405x over previous
#include <cuda_runtime.h>
#include <cstddef>
#include <cstdint>

// GRU_83133386982146: 2-layer GRU (H=10) + per-step linear 10->1.
// R13: R9 role split (15 FFMA2/step) + deep pipeline hiding the combine SHFL.
//   lanes  0- 9: L0 unit k (3 chains over h0)        -> h0(t+1)
//   lanes 10-19: L1 ih dots over h0(t) -> parked in pd registers
//   lanes 20-29: L1 hh dots over h1(t-2) + gates, consuming shfl(pd) of the
//                PREVIOUS iteration's ih-dots (shfl issued at loop top,
//                latency hidden under the FFMA2 chains) -> h1(t-1)
// 4th uniform chain = output linear over v (= h1 on HH lanes); staged and
// stored from HH lanes. Broadcast: double-buffered smem (STS+syncwarp+LDS,
// packed for fma.rn.f32x2). Sigmoid-side weights pre-scaled by 0.5.
// Pipeline fill: pdB init = 2e30 => first HH z-gate = 1 => h1(-1) = 0 exactly.

#define FULL 0xffffffffu

namespace {
constexpr int H = 10;
constexpr int T = 2048;
constexpr int B = 1024;
}

__device__ __forceinline__ float fast_tanh(float x) {
    float y;
    asm("tanh.approx.f32 %0, %1;" : "=f"(y) : "f"(x));
    return y;
}
__device__ __forceinline__ uint64_t pack2(float lo, float hi) {
    uint64_t r;
    asm("mov.b64 %0, {%1, %2};" : "=l"(r) : "f"(lo), "f"(hi));
    return r;
}
__device__ __forceinline__ float hadd2(uint64_t a) {
    float lo, hi;
    asm("mov.b64 {%0, %1}, %2;" : "=f"(lo), "=f"(hi) : "l"(a));
    return lo + hi;
}
__device__ __forceinline__ uint64_t ffma2(uint64_t a, uint64_t b, uint64_t c) {
    uint64_t d;
    asm("fma.rn.f32x2 %0, %1, %2, %3;" : "=l"(d) : "l"(a), "l"(b), "l"(c));
    return d;
}

__global__ void __launch_bounds__(32)
gru_warp_kernel(const float* __restrict__ x,
                const float* __restrict__ Wih0, const float* __restrict__ Whh0,
                const float* __restrict__ bih0, const float* __restrict__ bhh0,
                const float* __restrict__ Wih1, const float* __restrict__ Whh1,
                const float* __restrict__ bih1, const float* __restrict__ bhh1,
                const float* __restrict__ Wlin, const float* __restrict__ blin,
                float* __restrict__ out)
{
    const int b = blockIdx.x;
    const int lane = threadIdx.x;
    const bool isL0 = (lane < 10);
    const bool isIH = (lane >= 10 && lane < 20);
    const bool isHH = (lane >= 20);
    const int k = isL0 ? lane : (isIH ? (lane - 10)
                 : ((lane < 30) ? (lane - 20) : 9));

    // smem: [parity][40 floats]: h0 @0..9, h1 @12..21, scratch @24..39
    __shared__ __align__(16) float sbuf[2][40];

    // gate-row weight pairs; r/z rows pre-scaled by 0.5 (feed sigmoid)
    const float* WA = isL0 ? Whh0 : (isIH ? Wih1 : Whh1);
    uint64_t w0[5], w1[5], w2[5], w3[5];
#pragma unroll
    for (int j = 0; j < 5; j++) {
        w0[j] = pack2(0.5f * WA[k * H + 2 * j], 0.5f * WA[k * H + 2 * j + 1]);
        w1[j] = pack2(0.5f * WA[(H + k) * H + 2 * j],
                      0.5f * WA[(H + k) * H + 2 * j + 1]);
        w2[j] = pack2(WA[(2 * H + k) * H + 2 * j],
                      WA[(2 * H + k) * H + 2 * j + 1]);
        w3[j] = pack2(Wlin[2 * j], Wlin[2 * j + 1]);     // out dot (uniform)
    }
    // chain seeds (lo element)
    const float sA = isIH ? 0.5f * bih1[k] : 0.0f;
    const float sB = isIH ? 0.5f * bih1[H + k] : 0.0f;
    const float sCv = isL0 ? bhh0[2 * H + k]
                    : (isIH ? bih1[2 * H + k] : bhh1[2 * H + k]);
    const uint64_t seedA = pack2(sA, 0.0f);
    const uint64_t seedB = pack2(sB, 0.0f);
    const uint64_t seedC = pack2(sCv, 0.0f);
    const uint64_t seedO = pack2(blin[0], 0.0f);
    // scalar gate constants
    const float cxA = isL0 ? 0.5f * Wih0[k] : 0.0f;
    const float cxB = isL0 ? 0.5f * Wih0[H + k] : 0.0f;
    const float cxC = isL0 ? Wih0[2 * H + k] : 0.0f;
    const float btA = isL0 ? 0.5f * (bih0[k] + bhh0[k])
                           : (isHH ? 0.5f * bhh1[k] : 0.0f);
    const float btB = isL0 ? 0.5f * (bih0[H + k] + bhh0[H + k])
                           : (isHH ? 0.5f * bhh1[H + k] : 0.0f);
    const float btC = isL0 ? bih0[2 * H + k] : 0.0f;
    const float sel = isHH ? 1.0f : 0.0f;
    const int csrc = isHH ? (lane - 10) : lane;
    const int soff = isL0 ? lane
                   : (isIH ? (24 + (lane - 10))
                   : ((lane < 30) ? (12 + (lane - 20)) : (34 + (lane - 30))));
    const int vbase = (lane < 20) ? 0 : 12;
    const int ls = lane - 20;                 // out stage/store id (HH lanes)

    const float* xq = x + (size_t)b * T;
    float* orow = out + (size_t)b * T;

    float hown;
    uint64_t v[5];
    // parked ih-dots of the previous iteration (IH lanes meaningful)
    float pdA = 0.0f, pdB = 2.0e30f, pdC = 0.0f;   // pdB big => first z1 = 1

    // ---- preamble: h0(0) (hidden states zero -> dots vanish) ----
    {
        const float x0 = xq[0];
        const float pA = fmaf(cxA, x0, btA);
        const float pB = fmaf(cxB, x0, btB);
        const float tC = fmaf(cxC, x0, btC);
        const float r = fmaf(fast_tanh(pA), 0.5f, 0.5f);
        const float z = fmaf(fast_tanh(pB), 0.5f, 0.5f);
        const float n = fast_tanh(fmaf(r, sCv, tC));
        const float h0n = fmaf(z, 0.0f - n, n);
        hown = isL0 ? h0n : 0.0f;              // h1 state starts at 0
        sbuf[1][soff] = hown;                  // h0 slots = h0(0); h1 slots = 0
        __syncwarp();
        const ulonglong2 A0 = *(const ulonglong2*)&sbuf[1][vbase];
        const ulonglong2 A1 = *(const ulonglong2*)&sbuf[1][vbase + 4];
        v[0] = A0.x; v[1] = A0.y; v[2] = A1.x; v[3] = A1.y;
        v[4] = *(const uint64_t*)&sbuf[1][vbase + 8];
    }

    float xc = xq[1];          // x(t+1) for iteration t=0
    float obuf = 0.0f;
    int su = 7;                // becomes (t-2) mod 10 after top-of-loop bump

    // Invariant at top of iter t: v = h0(t) (lanes<20) | h1(t-2) (lanes>=20);
    // hown = h0(t)_k (L0) | h1(t-2)_k (HH); pd = ih-dots over h0(t-1).
    // Iter t computes h0(t+1), h1(t-1), and out(t-2).
#pragma unroll 2
    for (int t = 0; t < T; t++) {
        su = (su == 9) ? 0 : su + 1;
        // combine shfls issued FIRST -> 26-cyc latency hidden under chains
        const float gA = __shfl_sync(FULL, pdA, csrc);
        const float gB = __shfl_sync(FULL, pdB, csrc);
        const float gC = __shfl_sync(FULL, pdC, csrc);

        const int xi = (t + 2 < T) ? (t + 2) : (T - 1);
        const float xn_pref = xq[xi];

        // 4 packed chains, 5 FFMA2 each (r, z, n, out)
        uint64_t a0 = seedA, a1 = seedB, a2 = seedC, a3 = seedO;
#pragma unroll
        for (int j = 0; j < 5; j++) {
            a0 = ffma2(w0[j], v[j], a0);
            a1 = ffma2(w1[j], v[j], a1);
            a2 = ffma2(w2[j], v[j], a2);
            a3 = ffma2(w3[j], v[j], a3);
        }
        const float c0 = hadd2(a0), c1 = hadd2(a1), c2 = hadd2(a2);
        const float c3 = hadd2(a3);            // out(t-2) on HH lanes
        pdA = c0; pdB = c1; pdC = c2;          // park for next iteration

        const float tA = fmaf(cxA, xc, btA);
        const float tB = fmaf(cxB, xc, btB);
        const float tC = fmaf(cxC, xc, btC);

        const float preA = fmaf(sel, gA, c0 + tA);   // 0.5 * r pre-act
        const float preB = fmaf(sel, gB, c1 + tB);   // 0.5 * z pre-act
        const float r = fmaf(fast_tanh(preA), 0.5f, 0.5f);
        const float z = fmaf(fast_tanh(preB), 0.5f, 0.5f);
        const float q = fmaf(sel, gC, tC);
        const float n = fast_tanh(fmaf(r, c2, q));
        const float hnew = fmaf(z, hown - n, n);     // h0(t+1) | h1(t-1)
        hown = hnew;

        // broadcast (double-buffered smem, per-lane vector reload)
        const int p = t & 1;
        sbuf[p][soff] = hnew;
        __syncwarp();
        {
            const ulonglong2 A0 = *(const ulonglong2*)&sbuf[p][vbase];
            const ulonglong2 A1 = *(const ulonglong2*)&sbuf[p][vbase + 4];
            v[0] = A0.x; v[1] = A0.y; v[2] = A1.x; v[3] = A1.y;
            v[4] = *(const uint64_t*)&sbuf[p][vbase + 8];
        }

        // stage/store out(t-2) on HH lanes (early garbage overwritten)
        if (ls == su) obuf = c3;
        if (su == 9 && t > 10 && (unsigned)ls < 10u)
            orow[(t - 11) + ls] = obuf;

        xc = xn_pref;
    }

    // ---- epilogue: h1(T-1), out(T-2), out(T-1); rows 2040..2047 ----
    {
        // E1: h1(T-1) from pd = ih(h0(T-1)) and v = h1(T-2) on HH lanes
        const float gA = __shfl_sync(FULL, pdA, csrc);
        const float gB = __shfl_sync(FULL, pdB, csrc);
        const float gC = __shfl_sync(FULL, pdC, csrc);
        uint64_t a0 = seedA, a1 = seedB, a2 = seedC, a3 = seedO;
#pragma unroll
        for (int j = 0; j < 5; j++) {
            a0 = ffma2(w0[j], v[j], a0);
            a1 = ffma2(w1[j], v[j], a1);
            a2 = ffma2(w2[j], v[j], a2);
            a3 = ffma2(w3[j], v[j], a3);
        }
        const float c0 = hadd2(a0), c1 = hadd2(a1), c2 = hadd2(a2);
        const float c3 = hadd2(a3);                  // out(T-2) on HH lanes
        const float preA = fmaf(sel, gA, c0 + btA);
        const float preB = fmaf(sel, gB, c1 + btB);
        const float r = fmaf(fast_tanh(preA), 0.5f, 0.5f);
        const float z = fmaf(fast_tanh(preB), 0.5f, 0.5f);
        const float q = fmaf(sel, gC, 0.0f);
        const float n = fast_tanh(fmaf(r, c2, q));
        const float hnew = fmaf(z, hown - n, n);     // h1(T-1) on HH lanes
        if (ls == 6) obuf = c3;                      // out(2046), slot 6

        sbuf[0][soff] = hnew;
        __syncwarp();
        const ulonglong2 B0 = *(const ulonglong2*)&sbuf[0][vbase];
        const ulonglong2 B1 = *(const ulonglong2*)&sbuf[0][vbase + 4];
        v[0] = B0.x; v[1] = B0.y; v[2] = B1.x; v[3] = B1.y;
        v[4] = *(const uint64_t*)&sbuf[0][vbase + 8];

        // E2: out(T-1) = Wlin . h1(T-1)
        uint64_t aO = seedO;
#pragma unroll
        for (int j = 0; j < 5; j++) aO = ffma2(w3[j], v[j], aO);
        const float oO = hadd2(aO);
        if (ls == 7) obuf = oO;                      // out(2047), slot 7
        if ((unsigned)ls < 8u) orow[2040 + ls] = obuf;
    }
}

extern "C" void kernel_launch(void* const* d_in, const int* in_sizes, int n_in,
                              void* d_out, int out_size) {
    (void)in_sizes; (void)n_in; (void)out_size;
    const float* x    = (const float*)d_in[0];
    const float* Wih0 = (const float*)d_in[1];
    const float* Whh0 = (const float*)d_in[2];
    const float* bih0 = (const float*)d_in[3];
    const float* bhh0 = (const float*)d_in[4];
    const float* Wih1 = (const float*)d_in[5];
    const float* Whh1 = (const float*)d_in[6];
    const float* bih1 = (const float*)d_in[7];
    const float* bhh1 = (const float*)d_in[8];
    const float* Wlin = (const float*)d_in[9];
    const float* blin = (const float*)d_in[10];
    float* out = (float*)d_out;

    gru_warp_kernel<<<B, 32>>>(x, Wih0, Whh0, bih0, bhh0,
                               Wih1, Whh1, bih1, bhh1, Wlin, blin, out);
}

// round 15
// speedup vs baseline: 1.2555x; 1.2050x over previous
#include <cuda_runtime.h>
#include <cstddef>
#include <cstdint>

// GRU_83133386982146: 2-layer GRU (H=10) + per-step linear 10->1.
// R15 = R9 (best, 267us) + parked combine shfls (h1 lags one step so the 3
// combine SHFLs issue at loop top with ready operands; 26-cyc latency hidden
// under the FFMA2 chains). Everything else identical to R9:
//   lanes  0- 9: L0 unit k   (Whh0 rows . h0v), gates local
//   lanes 10-19: L1 ih dots  (Wih1 rows . h0v) -> parked in pd
//   lanes 20-29: L1 hh dots  (Whh1 rows . h1v) + L1 gates + h1 update
// smem double-buffered broadcast (1 STS + syncwarp + 3 LDS, packed for
// fma.rn.f32x2); h1 trajectory -> gmem planes; lin_kernel does the 10->1.

#define FULL 0xffffffffu

namespace {
constexpr int H = 10;
constexpr int T = 2048;
constexpr int B = 1024;
}

// h1 trajectory planes: [k][b*T + t]
__device__ __align__(16) float g_h1s[H][(size_t)B * T];

__device__ __forceinline__ float fast_tanh(float x) {
    float y;
    asm("tanh.approx.f32 %0, %1;" : "=f"(y) : "f"(x));
    return y;
}
__device__ __forceinline__ float fast_sigmoid(float x) {
    return fmaf(fast_tanh(0.5f * x), 0.5f, 0.5f);
}
__device__ __forceinline__ uint64_t pack2(float lo, float hi) {
    uint64_t r;
    asm("mov.b64 %0, {%1, %2};" : "=l"(r) : "f"(lo), "f"(hi));
    return r;
}
__device__ __forceinline__ float hadd2(uint64_t a) {
    float lo, hi;
    asm("mov.b64 {%0, %1}, %2;" : "=f"(lo), "=f"(hi) : "l"(a));
    return lo + hi;
}
__device__ __forceinline__ uint64_t ffma2(uint64_t a, uint64_t b, uint64_t c) {
    uint64_t d;
    asm("fma.rn.f32x2 %0, %1, %2, %3;" : "=l"(d) : "l"(a), "l"(b), "l"(c));
    return d;
}

__global__ void __launch_bounds__(32)
gru_warp_kernel(const float* __restrict__ x,
                const float* __restrict__ Wih0, const float* __restrict__ Whh0,
                const float* __restrict__ bih0, const float* __restrict__ bhh0,
                const float* __restrict__ Wih1, const float* __restrict__ Whh1,
                const float* __restrict__ bih1, const float* __restrict__ bhh1)
{
    const int b = blockIdx.x;
    const int lane = threadIdx.x;
    const int cl = (lane < 30) ? lane : 29;
    const bool isL0 = (lane < 10);
    const bool isIH = (lane >= 10 && lane < 20);
    const bool isHH = (lane >= 20);
    const int k = cl % 10;

    // smem: [parity][40 floats]: h0 @0..9, h1 @12..21, scratch @24..39
    __shared__ __align__(16) float sbuf[2][40];

    const float* Wsrc = isL0 ? Whh0 : (isIH ? Wih1 : Whh1);

    // packed gate-row weights (A=r, B=z, C=n)
    uint64_t wa[5], wb[5], wc[5];
#pragma unroll
    for (int j = 0; j < 5; j++) {
        wa[j] = pack2(Wsrc[k * H + 2 * j],           Wsrc[k * H + 2 * j + 1]);
        wb[j] = pack2(Wsrc[(H + k) * H + 2 * j],     Wsrc[(H + k) * H + 2 * j + 1]);
        wc[j] = pack2(Wsrc[(2 * H + k) * H + 2 * j], Wsrc[(2 * H + k) * H + 2 * j + 1]);
    }
    const float cxA = isL0 ? Wih0[k] : 0.0f;
    const float cxB = isL0 ? Wih0[H + k] : 0.0f;
    const float cxC = isL0 ? Wih0[2 * H + k] : 0.0f;
    const float sA = isIH ? bih1[k] : 0.0f;
    const float sB = isIH ? bih1[H + k] : 0.0f;
    const float sC = isL0 ? bhh0[2 * H + k]
                   : (isIH ? bih1[2 * H + k] : bhh1[2 * H + k]);
    const uint64_t seedA = pack2(sA, 0.0f);
    const uint64_t seedB = pack2(sB, 0.0f);
    const uint64_t seedC = pack2(sC, 0.0f);
    const float btA = isL0 ? (bih0[k] + bhh0[k]) : (isHH ? bhh1[k] : 0.0f);
    const float btB = isL0 ? (bih0[H + k] + bhh0[H + k])
                           : (isHH ? bhh1[H + k] : 0.0f);
    const float btC = isL0 ? bih0[2 * H + k] : 0.0f;
    const float sel = isHH ? 1.0f : 0.0f;
    const int csrc = isHH ? (lane - 10) : lane;

    const int soff = (lane < 10) ? lane
                   : (lane < 20) ? (24 + (lane - 10))
                   : (lane < 30) ? (12 + (lane - 20))
                                 : (34 + (lane - 30));
    const int vbase = (lane < 20) ? 0 : 12;

    const float* xq = x + (size_t)b * T;
    float* h1row = &g_h1s[k][(size_t)b * T];
    const bool hstore = (lane >= 20) && (lane < 30);

    float hown;
    uint64_t v[5];
    // parked ih-dots from previous iteration; pdB huge => first z1 = 1
    float pdA = 0.0f, pdB = 2.0e30f, pdC = 0.0f;

    // ---- preamble: h0(0)  (states zero -> hidden dots vanish) ----
    {
        const float x0 = xq[0];
        const float tA = fmaf(cxA, x0, btA);
        const float tB = fmaf(cxB, x0, btB);
        const float tC = fmaf(cxC, x0, btC);
        const float r = fast_sigmoid(tA);
        const float z = fast_sigmoid(tB);
        const float n = fast_tanh(fmaf(r, sC, tC));
        const float h0n = fmaf(z, 0.0f - n, n);     // valid on L0 lanes
        hown = isL0 ? h0n : 0.0f;                   // h1 state starts 0
#pragma unroll
        for (int j = 0; j < 5; j++) {
            const float lo = __shfl_sync(FULL, h0n, 2 * j);
            const float hi = __shfl_sync(FULL, h0n, 2 * j + 1);
            v[j] = (lane < 20) ? pack2(lo, hi) : pack2(0.0f, 0.0f);
        }
    }

    float xc = xq[1];                 // x(t+1) for iteration t=0
    float ob[4] = {0.f, 0.f, 0.f, 0.f};

    // Invariant at top of iter t: v = h0(t) on lanes<20, h1(t-2) on lanes>=20;
    // hown = h0(t)_k (L0) | h1(t-2)_k (HH); pd = ih-dots over h0(t-1).
    // Iter t computes h0(t+1) (L0) and h1(t-1) (HH).
    for (int t0 = 0; t0 < T; t0 += 4) {
#pragma unroll
        for (int u = 0; u < 4; u++) {
            const int t = t0 + u;
            // combine shfls FIRST (operands from last iter -> latency hidden)
            const float gA = __shfl_sync(FULL, pdA, csrc);
            const float gB = __shfl_sync(FULL, pdB, csrc);
            const float gC = __shfl_sync(FULL, pdC, csrc);

            const int xi = (t + 2 < T) ? (t + 2) : (T - 1);
            const float xn_pref = xq[xi];

            // 3 packed dot chains, 5 FFMA2 each
            uint64_t aA = seedA, aB = seedB, aC = seedC;
#pragma unroll
            for (int j = 0; j < 5; j++) {
                aA = ffma2(wa[j], v[j], aA);
                aB = ffma2(wb[j], v[j], aB);
                aC = ffma2(wc[j], v[j], aC);
            }
            const float dotA = hadd2(aA);
            const float dotB = hadd2(aB);
            const float dotC = hadd2(aC);
            pdA = dotA; pdB = dotB; pdC = dotC;      // park for next iter

            const float tA = fmaf(cxA, xc, btA);
            const float tB = fmaf(cxB, xc, btB);
            const float tC = fmaf(cxC, xc, btC);

            const float preA = fmaf(sel, gA, dotA + tA);
            const float preB = fmaf(sel, gB, dotB + tB);
            const float r = fast_sigmoid(preA);
            const float z = fast_sigmoid(preB);
            const float q = fmaf(sel, gC, tC);
            const float n = fast_tanh(fmaf(r, dotC, q));
            const float hnew = fmaf(z, hown - n, n); // h0(t+1) | h1(t-1)
            hown = hnew;

            // stage h1(t-1) in circular slot (u+3)&3; store at u==0 (aligned)
            ob[(u + 3) & 3] = hnew;
            if (u == 0 && t0 >= 4 && hstore)
                *(float4*)&h1row[t0 - 4] = make_float4(ob[0], ob[1], ob[2], ob[3]);

            // broadcast via double-buffered smem, packed reload
            const int p = u & 1;
            sbuf[p][soff] = hnew;
            __syncwarp();
            {
                const ulonglong2 A0 = *(const ulonglong2*)&sbuf[p][vbase];
                const ulonglong2 A1 = *(const ulonglong2*)&sbuf[p][vbase + 4];
                v[0] = A0.x; v[1] = A0.y; v[2] = A1.x; v[3] = A1.y;
                v[4] = *(const uint64_t*)&sbuf[p][vbase + 8];
            }

            xc = xn_pref;
        }
    }

    // ---- epilogue: one more HH half-step -> h1(T-1); store last 4 ----
    {
        const float gA = __shfl_sync(FULL, pdA, csrc);
        const float gB = __shfl_sync(FULL, pdB, csrc);
        const float gC = __shfl_sync(FULL, pdC, csrc);
        uint64_t aA = seedA, aB = seedB, aC = seedC;
#pragma unroll
        for (int j = 0; j < 5; j++) {
            aA = ffma2(wa[j], v[j], aA);
            aB = ffma2(wb[j], v[j], aB);
            aC = ffma2(wc[j], v[j], aC);
        }
        const float dotA = hadd2(aA);
        const float dotB = hadd2(aB);
        const float dotC = hadd2(aC);
        const float preA = fmaf(sel, gA, dotA + btA);
        const float preB = fmaf(sel, gB, dotB + btB);
        const float r = fast_sigmoid(preA);
        const float z = fast_sigmoid(preB);
        const float q = fmaf(sel, gC, btC);
        const float n = fast_tanh(fmaf(r, dotC, q));
        const float hnew = fmaf(z, hown - n, n);     // h1(T-1) on HH lanes
        ob[3] = hnew;
        if (hstore)
            *(float4*)&h1row[T - 4] = make_float4(ob[0], ob[1], ob[2], ob[3]);
    }
}

__global__ void __launch_bounds__(256)
lin_kernel(const float* __restrict__ Wlin, const float* __restrict__ blin,
           float* __restrict__ out)
{
    const int i4 = (blockIdx.x * blockDim.x + threadIdx.x) * 4;
    if (i4 >= B * T) return;
    const float bl = blin[0];
    float a0 = bl, a1 = bl, a2 = bl, a3 = bl;
#pragma unroll
    for (int k = 0; k < H; k++) {
        const float w = Wlin[k];
        const float4 h = *(const float4*)&g_h1s[k][i4];
        a0 = fmaf(w, h.x, a0);
        a1 = fmaf(w, h.y, a1);
        a2 = fmaf(w, h.z, a2);
        a3 = fmaf(w, h.w, a3);
    }
    *(float4*)&out[i4] = make_float4(a0, a1, a2, a3);
}

extern "C" void kernel_launch(void* const* d_in, const int* in_sizes, int n_in,
                              void* d_out, int out_size) {
    (void)in_sizes; (void)n_in; (void)out_size;
    const float* x    = (const float*)d_in[0];
    const float* Wih0 = (const float*)d_in[1];
    const float* Whh0 = (const float*)d_in[2];
    const float* bih0 = (const float*)d_in[3];
    const float* bhh0 = (const float*)d_in[4];
    const float* Wih1 = (const float*)d_in[5];
    const float* Whh1 = (const float*)d_in[6];
    const float* bih1 = (const float*)d_in[7];
    const float* bhh1 = (const float*)d_in[8];
    const float* Wlin = (const float*)d_in[9];
    const float* blin = (const float*)d_in[10];
    float* out = (float*)d_out;

    gru_warp_kernel<<<B, 32>>>(x, Wih0, Whh0, bih0, bhh0,
                               Wih1, Whh1, bih1, bhh1);
    lin_kernel<<<(B * T / 4 + 255) / 256, 256>>>(Wlin, blin, out);
}